// round 16
// baseline (speedup 1.0000x reference)
#include <cuda_runtime.h>
#include <cuda_bf16.h>
#include <math.h>

typedef unsigned long long ull;
typedef unsigned int u32;

// ---------------- mma helpers ----------------
#define LDSM_X4(r0,r1,r2,r3,addr) \
  asm volatile("ldmatrix.sync.aligned.m8n8.x4.shared.b16 {%0,%1,%2,%3},[%4];" \
    : "=r"(r0),"=r"(r1),"=r"(r2),"=r"(r3) : "r"(addr))

#define MMA_BF16(d,a0,a1,a2,a3,b0,b1) \
  asm volatile("mma.sync.aligned.m16n8k16.row.col.f32.bf16.bf16.f32 " \
    "{%0,%1,%2,%3},{%4,%5,%6,%7},{%8,%9},{%0,%1,%2,%3};" \
    : "+f"((d)[0]),"+f"((d)[1]),"+f"((d)[2]),"+f"((d)[3]) \
    : "r"(a0),"r"(a1),"r"(a2),"r"(a3),"r"(b0),"r"(b1))

// ---------------- static device scratch ----------------
__device__ float g_A[64u*256u*32u*32u];
__device__ float g_B[64u*256u*32u*32u];
__device__ float g_H0[64u*256u*16u*16u];
__device__ float g_SC[64u*256u*16u*16u];
__device__ float g_T8[64u*256u*8u*8u];
__device__ float g_H1[64u*256u*8u*8u];
__device__ float g_H2[64u*256u*8u*8u];
__device__ float g_H3[64u*256u*8u*8u];
__device__ float g_PX[64u*3u*16u*16u];

__device__ float g_sw0[6912];
__device__ float g_sw2[768];
__device__ float g_sw5[65536];
__device__ float g_swlin[256];
__device__ float g_swemb[25600];

__device__ __nv_bfloat16 g_wbh[7u*589824u];
__device__ __nv_bfloat16 g_wbl[7u*589824u];
__device__ __nv_bfloat16 g_cbh[4u*262144u];
__device__ __nv_bfloat16 g_cbl[4u*262144u];

__device__ float g_sigma[12];
__device__ float g_sv[12*2304];
__device__ float g_p1[96];
__device__ float g_p2[96];
__device__ float g_enorm4[4*1024];
__device__ float2 g_cand[16384*16];
__device__ float g_xnorm[16384];
__device__ float g_qloss[64];
__device__ int   g_hist[1024];
__device__ float g_hf[64*256];

// ---------------- spectral norm (parallel, deterministic) ----------------
struct SnDesc { const float* w; float* out; __nv_bfloat16* oh; __nv_bfloat16* ol;
                int O; int R; int mode; };
struct SnArgs { SnDesc d[12]; };

__global__ void init_zero_k() {
    int i = blockIdx.x * blockDim.x + threadIdx.x;
    if (i < 1024) g_hist[i] = 0;
    if (i < 64)   g_qloss[i] = 0.f;
}

__global__ void sn_col_k(SnArgs a) {
    __shared__ float red[256];
    const int w = blockIdx.x, seg = blockIdx.y, tid = threadIdx.x;
    const SnDesc d = a.d[w];
    const int O = d.O, R = d.R;
    const int Rper = (R + 7) / 8;
    const int j0 = seg * Rper;
    const int j1 = (j0 + Rper < R) ? (j0 + Rper) : R;
    const float is = rsqrtf((float)O);
    float loc = 0.f;
    for (int j = j0 + tid; j < j1; j += 256) {
        float s = 0.f;
#pragma unroll 4
        for (int i = 0; i < O; i++) s += d.w[(size_t)i * R + j];
        s *= is;
        g_sv[w * 2304 + j] = s;
        loc += s * s;
    }
    red[tid] = loc; __syncthreads();
    for (int s = 128; s > 0; s >>= 1) { if (tid < s) red[tid] += red[tid + s]; __syncthreads(); }
    if (tid == 0) g_p1[w * 8 + seg] = red[0];
}

__global__ void sn_row_k(SnArgs a) {
    __shared__ float red[256];
    const int w = blockIdx.x, seg = blockIdx.y, tid = threadIdx.x;
    const int wid = tid >> 5, lane = tid & 31;
    const SnDesc d = a.d[w];
    const int O = d.O, R = d.R;
    float s1 = 0.f;
#pragma unroll
    for (int s = 0; s < 8; s++) s1 += g_p1[w * 8 + s];
    const float fv = 1.f / (sqrtf(s1) + 1e-8f);
    const int Oper = (O + 7) / 8;
    const int i0 = seg * Oper;
    const int i1 = (i0 + Oper < O) ? (i0 + Oper) : O;
    const float* sv = &g_sv[w * 2304];
    float loc = 0.f;
    for (int i = i0 + wid; i < i1; i += 8) {
        float t = 0.f;
        const float* row = d.w + (size_t)i * R;
        for (int j = lane; j < R; j += 32) t += row[j] * sv[j];
#pragma unroll
        for (int off = 16; off; off >>= 1) t += __shfl_xor_sync(0xffffffffu, t, off);
        t *= fv;
        if (lane == 0) loc += t * t;
    }
    red[tid] = loc; __syncthreads();
    for (int s = 128; s > 0; s >>= 1) { if (tid < s) red[tid] += red[tid + s]; __syncthreads(); }
    if (tid == 0) g_p2[w * 8 + seg] = red[0];
}

__global__ void sn_fin_k() {
    int w = threadIdx.x;
    if (w >= 12) return;
    float s = 0.f;
#pragma unroll
    for (int i = 0; i < 8; i++) s += g_p2[w * 8 + i];
    g_sigma[w] = s / (sqrtf(s) + 1e-8f);
}

__global__ void sn_scale_k(SnArgs a, int base) {
    const int w = base + blockIdx.x;
    const SnDesc d = a.d[w];
    const float inv = 1.f / g_sigma[w];
    const int n = d.O * d.R, stride = gridDim.y * blockDim.x;
    for (int e = blockIdx.y * blockDim.x + threadIdx.x; e < n; e += stride) {
        float v = d.w[e] * inv;
        if (d.mode == 0) {
            d.out[e] = v;
        } else if (d.mode == 1) {
            int o = e / d.R, rr = e % d.R;
            d.out[(size_t)rr * d.O + o] = v;
        } else {
            int o = e / d.R, rem = e % d.R;
            int c = rem / 9, tap = rem % 9;
            size_t oi = ((size_t)tap * d.O + o) * (d.R / 9) + c;
            __nv_bfloat16 h = __float2bfloat16(v);
            d.oh[oi] = h;
            d.ol[oi] = __float2bfloat16(v - __bfloat162float(h));
        }
    }
}

__global__ void enorm_k(const float* __restrict__ cb, float* __restrict__ en) {
    int k = blockIdx.x * blockDim.x + threadIdx.x;
    if (k >= 1024) return;
    float s = 0.f;
#pragma unroll 4
    for (int c = 0; c < 256; c++) { float v = cb[(size_t)c * 1024 + k]; s += v * v; }
    en[k] = s;
}

__global__ void cbt_k(const float* __restrict__ cb,
                      __nv_bfloat16* __restrict__ oh, __nv_bfloat16* __restrict__ ol) {
    int idx = blockIdx.x * 256 + threadIdx.x;
    int code = idx & 1023, c = idx >> 10;
    float v = cb[(size_t)c * 1024 + code];
    __nv_bfloat16 h = __float2bfloat16(v);
    oh[(size_t)code * 256 + c] = h;
    ol[(size_t)code * 256 + c] = __float2bfloat16(v - __bfloat162float(h));
}

// ---------------- mma conv3x3 (C multiple of 16, W==TW), NOC oc per block ----------------
// Inner loop: 3 passes (hh, h*lo, lo*h) across all tile-groups -> acc reuse distance 2*NT.
template<int TH, int TW, int G, int NOC>
__global__ void __launch_bounds__(256) conv_mma_k(
    const float* __restrict__ in, const __nv_bfloat16* __restrict__ wh,
    const __nv_bfloat16* __restrict__ wl, const float* __restrict__ bias,
    const float* __restrict__ res, float* __restrict__ out,
    int C, int O, int H, int relu_in)
{
    constexpr int PH = TH + 2, PWW = TW + 2, NPX = G * PH * PWW, AST = 24;
    constexpr int W = TW;
    constexpr int NT = NOC / 16;
    constexpr int NA = NOC / 8;
    extern __shared__ __align__(16) char smraw[];
    __nv_bfloat16* sAh = (__nv_bfloat16*)smraw;
    __nv_bfloat16* sAl = sAh + NPX * AST;
    __nv_bfloat16* sBh = sAl + NPX * AST;
    __nv_bfloat16* sBl = sBh + 9 * NOC * AST;

    const int tid = threadIdx.x, wi = tid >> 5, lane = tid & 31;
    const int obase = blockIdx.x * NOC;
    const int TPI = H / TH;
    const int tileY = (G == 1) ? (blockIdx.y % TPI) : 0;
    const int imgb  = (G == 1) ? (blockIdx.y / TPI) : blockIdx.y * G;

    const int p = wi * 16 + (lane & 15);
    const int fg = p / (TH * TW), fr = p % (TH * TW), fpy = fr / TW, fpx = fr % TW;
    const u32 aRow = (u32)((fg * PH + fpy) * PWW + fpx);
    const u32 aH = (u32)__cvta_generic_to_shared(sAh) + (aRow * AST + (lane >> 4) * 8) * 2;
    const u32 aL = (u32)__cvta_generic_to_shared(sAl) + (aRow * AST + (lane >> 4) * 8) * 2;
    const int l8 = lane & 7, seg = lane >> 3;
    const u32 bRow = (u32)((((seg >> 1) * 8 + l8) * AST + (seg & 1) * 8) * 2);
    const u32 bH0 = (u32)__cvta_generic_to_shared(sBh) + bRow;
    const u32 bL0 = (u32)__cvta_generic_to_shared(sBl) + bRow;

    float acc[NA][4];
#pragma unroll
    for (int t = 0; t < NA; t++) { acc[t][0]=acc[t][1]=acc[t][2]=acc[t][3]=0.f; }

    const int nch = C / 16;
    for (int ck = 0; ck < nch; ck++) {
        const int c0 = ck * 16;
        __syncthreads();
        for (int idx = tid; idx < NPX * 16; idx += 256) {
            int ch = idx / NPX, r = idx % NPX;
            int gg = r / (PH * PWW), r2 = r % (PH * PWW);
            int py = r2 / PWW, pxx = r2 % PWW;
            int gy = tileY * TH + py - 1, gx = pxx - 1;
            float v = 0.f;
            if ((unsigned)gy < (unsigned)H && (unsigned)gx < (unsigned)W)
                v = in[(((size_t)(imgb + gg) * C + c0 + ch) * H + gy) * W + gx];
            if (relu_in) v = fmaxf(v, 0.f);
            __nv_bfloat16 h = __float2bfloat16(v);
            sAh[r * AST + ch] = h;
            sAl[r * AST + ch] = __float2bfloat16(v - __bfloat162float(h));
        }
        for (int idx = tid; idx < 9 * NOC * 2; idx += 256) {
            int half = idx & 1, o = (idx >> 1) % NOC, tap = (idx >> 1) / NOC;
            size_t ga = ((size_t)(tap * O + obase + o)) * C + c0 + half * 8;
            int so = (tap * NOC + o) * AST + half * 8;
            *(uint4*)(sBh + so) = *(const uint4*)(wh + ga);
            *(uint4*)(sBl + so) = *(const uint4*)(wl + ga);
        }
        __syncthreads();

#pragma unroll
        for (int tap = 0; tap < 9; tap++) {
            const int dy = tap / 3, dx = tap % 3;
            const u32 sh = (u32)((dy * PWW + dx) * AST * 2);
            u32 ah0,ah1,ah2,ah3, al0,al1,al2,al3;
            LDSM_X4(ah0,ah1,ah2,ah3, aH + sh);
            LDSM_X4(al0,al1,al2,al3, aL + sh);
            u32 bh[NT][4], bl[NT][4];
#pragma unroll
            for (int tg = 0; tg < NT; tg++) {
                const u32 off = (u32)((tap * NOC + tg * 16) * AST * 2);
                LDSM_X4(bh[tg][0],bh[tg][1],bh[tg][2],bh[tg][3], bH0 + off);
                LDSM_X4(bl[tg][0],bl[tg][1],bl[tg][2],bl[tg][3], bL0 + off);
            }
            // pass 1: a_hi * b_hi
#pragma unroll
            for (int tg = 0; tg < NT; tg++) {
                MMA_BF16(acc[2*tg],   ah0,ah1,ah2,ah3, bh[tg][0],bh[tg][1]);
                MMA_BF16(acc[2*tg+1], ah0,ah1,ah2,ah3, bh[tg][2],bh[tg][3]);
            }
            // pass 2: a_hi * b_lo
#pragma unroll
            for (int tg = 0; tg < NT; tg++) {
                MMA_BF16(acc[2*tg],   ah0,ah1,ah2,ah3, bl[tg][0],bl[tg][1]);
                MMA_BF16(acc[2*tg+1], ah0,ah1,ah2,ah3, bl[tg][2],bl[tg][3]);
            }
            // pass 3: a_lo * b_hi
#pragma unroll
            for (int tg = 0; tg < NT; tg++) {
                MMA_BF16(acc[2*tg],   al0,al1,al2,al3, bh[tg][0],bh[tg][1]);
                MMA_BF16(acc[2*tg+1], al0,al1,al2,al3, bh[tg][2],bh[tg][3]);
            }
        }
    }

    const int q = lane >> 2, cp = (lane & 3) * 2;
#pragma unroll
    for (int rI = 0; rI < 2; rI++) {
        int pp = wi * 16 + q + rI * 8;
        int gg = pp / (TH * TW), r = pp % (TH * TW), py = r / TW, px = r % TW;
        int img = imgb + gg, y = tileY * TH + py;
        size_t pixoff = (((size_t)img * O) * H + y) * W + px;
#pragma unroll
        for (int t = 0; t < NA; t++) {
            int oc = obase + t * 8 + cp;
            size_t a0 = pixoff + (size_t)oc * H * W;
            size_t a1 = a0 + (size_t)H * W;
            float v0 = acc[t][rI * 2 + 0] + bias[oc];
            float v1 = acc[t][rI * 2 + 1] + bias[oc + 1];
            if (res) { v0 += res[a0]; v1 += res[a1]; }
            out[a0] = v0; out[a1] = v1;
        }
    }
}

// ---------------- mma VQ (same 3-pass restructure) ----------------
__global__ void __launch_bounds__(256) vq_mma_k(
    const float* __restrict__ h, const __nv_bfloat16* __restrict__ cbh,
    const __nv_bfloat16* __restrict__ cbl, const float* __restrict__ enorm,
    int C, int lhw)
{
    constexpr int AST = 24;
    __shared__ __align__(16) __nv_bfloat16 sAh[128 * AST];
    __shared__ __align__(16) __nv_bfloat16 sAl[128 * AST];
    __shared__ __align__(16) __nv_bfloat16 sBh[64 * AST];
    __shared__ __align__(16) __nv_bfloat16 sBl[64 * AST];

    const int tid = threadIdx.x, wi = tid >> 5, lane = tid & 31;
    const int ktile = blockIdx.x, pbase = blockIdx.y * 128;
    const int hwm = (1 << lhw) - 1;

    const int p = wi * 16 + (lane & 15);
    const u32 aH = (u32)__cvta_generic_to_shared(sAh) + (p * AST + (lane >> 4) * 8) * 2;
    const u32 aL = (u32)__cvta_generic_to_shared(sAl) + (p * AST + (lane >> 4) * 8) * 2;
    const int l8 = lane & 7, seg = lane >> 3;
    const u32 bRow = (u32)((((seg >> 1) * 8 + l8) * AST + (seg & 1) * 8) * 2);
    const u32 bH0 = (u32)__cvta_generic_to_shared(sBh) + bRow;
    const u32 bL0 = (u32)__cvta_generic_to_shared(sBl) + bRow;

    float acc[8][4];
#pragma unroll
    for (int t = 0; t < 8; t++) { acc[t][0]=acc[t][1]=acc[t][2]=acc[t][3]=0.f; }

    for (int ck = 0; ck < C / 16; ck++) {
        const int c0 = ck * 16;
        __syncthreads();
        for (int idx = tid; idx < 512; idx += 256) {
            int ch = idx >> 5, grp = idx & 31;
            int i = grp * 4;
            int pg = pbase + i, b = pg >> lhw, hw = pg & hwm;
            float4 v = *(const float4*)(h + (((size_t)b * C + c0 + ch) << lhw) + hw);
            float vs[4] = { v.x, v.y, v.z, v.w };
#pragma unroll
            for (int j = 0; j < 4; j++) {
                __nv_bfloat16 hv = __float2bfloat16(vs[j]);
                sAh[(i + j) * AST + ch] = hv;
                sAl[(i + j) * AST + ch] = __float2bfloat16(vs[j] - __bfloat162float(hv));
            }
        }
        for (int idx = tid; idx < 128; idx += 256) {
            int half = idx & 1, code = idx >> 1;
            size_t ga = (size_t)(ktile * 64 + code) * 256 + c0 + half * 8;
            int so = code * AST + half * 8;
            *(uint4*)(sBh + so) = *(const uint4*)(cbh + ga);
            *(uint4*)(sBl + so) = *(const uint4*)(cbl + ga);
        }
        __syncthreads();

        u32 ah0,ah1,ah2,ah3, al0,al1,al2,al3;
        LDSM_X4(ah0,ah1,ah2,ah3, aH);
        LDSM_X4(al0,al1,al2,al3, aL);
        u32 bh[4][4], bl[4][4];
#pragma unroll
        for (int tg = 0; tg < 4; tg++) {
            const u32 off = (u32)(tg * 16 * AST * 2);
            LDSM_X4(bh[tg][0],bh[tg][1],bh[tg][2],bh[tg][3], bH0 + off);
            LDSM_X4(bl[tg][0],bl[tg][1],bl[tg][2],bl[tg][3], bL0 + off);
        }
#pragma unroll
        for (int tg = 0; tg < 4; tg++) {
            MMA_BF16(acc[2*tg],   ah0,ah1,ah2,ah3, bh[tg][0],bh[tg][1]);
            MMA_BF16(acc[2*tg+1], ah0,ah1,ah2,ah3, bh[tg][2],bh[tg][3]);
        }
#pragma unroll
        for (int tg = 0; tg < 4; tg++) {
            MMA_BF16(acc[2*tg],   ah0,ah1,ah2,ah3, bl[tg][0],bl[tg][1]);
            MMA_BF16(acc[2*tg+1], ah0,ah1,ah2,ah3, bl[tg][2],bl[tg][3]);
        }
#pragma unroll
        for (int tg = 0; tg < 4; tg++) {
            MMA_BF16(acc[2*tg],   al0,al1,al2,al3, bh[tg][0],bh[tg][1]);
            MMA_BF16(acc[2*tg+1], al0,al1,al2,al3, bh[tg][2],bh[tg][3]);
        }
    }

    const int q = lane >> 2, cp = (lane & 3) * 2;
#pragma unroll
    for (int rI = 0; rI < 2; rI++) {
        float bv = -1e30f; int bi = 0;
#pragma unroll
        for (int t = 0; t < 8; t++) {
            int code = ktile * 64 + t * 8 + cp;
            float s0 = acc[t][rI * 2 + 0] - 0.5f * enorm[code];
            float s1 = acc[t][rI * 2 + 1] - 0.5f * enorm[code + 1];
            if (s0 > bv) { bv = s0; bi = code; }
            if (s1 > bv) { bv = s1; bi = code + 1; }
        }
#pragma unroll
        for (int off = 1; off <= 2; off <<= 1) {
            float ov = __shfl_down_sync(0xffffffffu, bv, off);
            int   oi = __shfl_down_sync(0xffffffffu, bi, off);
            if (ov > bv || (ov == bv && oi < bi)) { bv = ov; bi = oi; }
        }
        if ((lane & 3) == 0) {
            int pg = pbase + wi * 16 + q + rI * 8;
            g_cand[(size_t)pg * 16 + ktile] = make_float2(bv, __int_as_float(bi));
        }
    }
}

// ---------------- scalar conv3x3 (only for C=3 first conv) ----------------
__device__ __forceinline__ ull pk2(float lo, float hi) {
    ull r; asm("mov.b64 %0,{%1,%2};" : "=l"(r) : "f"(lo), "f"(hi)); return r;
}
__device__ __forceinline__ void upk2(float& lo, float& hi, ull v) {
    asm("mov.b64 {%0,%1},%2;" : "=f"(lo), "=f"(hi) : "l"(v));
}
__device__ __forceinline__ ull fma2(ull a, ull b, ull c) {
    ull d; asm("fma.rn.f32x2 %0,%1,%2,%3;" : "=l"(d) : "l"(a), "l"(b), "l"(c)); return d;
}

template<int TH, int TW, int G, int NC>
__global__ void __launch_bounds__(256) conv3x3_k(
    const float* __restrict__ in, const float* __restrict__ wt,
    const float* __restrict__ bias, float* __restrict__ out,
    int C, int O, int H, int W, int relu_in)
{
    constexpr int PH = TH + 2, PW = TW + 4, XG = TW / 4;
    constexpr int SROW = TW + 2;
    __shared__ __align__(16) float s_in[NC * G * PH * PW];
    __shared__ __align__(16) float s_w2[NC * 576];
    const int tid = threadIdx.x, ot = tid >> 5, pt = tid & 31;
    const int g = pt / (TH * XG), r = pt % (TH * XG), row = r / XG, xg = r % XG;
    const int tilesX = W / TW;
    const int tileY = blockIdx.y / tilesX, tileX = blockIdx.y % tilesX;
    const int img = blockIdx.z * G + g, obase = blockIdx.x * 64;

    ull acc2[4][4];
#pragma unroll
    for (int p = 0; p < 4; p++)
#pragma unroll
        for (int px = 0; px < 4; px++) acc2[p][px] = 0ull;

    for (int c0 = 0; c0 < C; c0 += NC) {
        __syncthreads();
        for (int idx = tid; idx < NC * G * PH * SROW; idx += 256) {
            int cc = idx / (G * PH * SROW);
            int r3 = idx % (G * PH * SROW);
            int gg = r3 / (PH * SROW);
            int r2 = r3 % (PH * SROW);
            int py = r2 / SROW, px = r2 % SROW;
            int gy = tileY * TH + py - 1, gx = tileX * TW + px - 1;
            float v = 0.f;
            if ((unsigned)gy < (unsigned)H && (unsigned)gx < (unsigned)W)
                v = in[(((size_t)(blockIdx.z * G + gg) * C + c0 + cc) * H + gy) * W + gx];
            if (relu_in) v = fmaxf(v, 0.f);
            s_in[(cc * G + gg) * PH * PW + py * PW + px] = v;
        }
        for (int idx = tid; idx < NC * 576; idx += 256) {
            int cc = idx / 576, r2 = idx % 576;
            int k = r2 >> 6, o = r2 & 63;
            s_w2[cc * 576 + (o >> 1) * 18 + k * 2 + (o & 1)] =
                wt[((size_t)(c0 + cc) * 9 + k) * O + obase + o];
        }
        __syncthreads();

#pragma unroll 1
        for (int cc = 0; cc < NC; cc++) {
            const float* sp = &s_in[(cc * G + g) * PH * PW + row * PW + xg * 4];
            const ull* wp = (const ull*)&s_w2[cc * 576 + ot * 72];
#pragma unroll
            for (int dy = 0; dy < 3; dy++) {
                float4 v4 = *(const float4*)(sp + dy * PW);
                float2 v2 = *(const float2*)(sp + dy * PW + 4);
                ull ivb[6];
                ivb[0] = pk2(v4.x, v4.x); ivb[1] = pk2(v4.y, v4.y);
                ivb[2] = pk2(v4.z, v4.z); ivb[3] = pk2(v4.w, v4.w);
                ivb[4] = pk2(v2.x, v2.x); ivb[5] = pk2(v2.y, v2.y);
#pragma unroll
                for (int dx = 0; dx < 3; dx++) {
                    const int k = dy * 3 + dx;
#pragma unroll
                    for (int p = 0; p < 4; p++) {
                        ull w = wp[p * 9 + k];
                        acc2[p][0] = fma2(w, ivb[dx + 0], acc2[p][0]);
                        acc2[p][1] = fma2(w, ivb[dx + 1], acc2[p][1]);
                        acc2[p][2] = fma2(w, ivb[dx + 2], acc2[p][2]);
                        acc2[p][3] = fma2(w, ivb[dx + 3], acc2[p][3]);
                    }
                }
            }
        }
    }

    const int y = tileY * TH + row, x = tileX * TW + xg * 4;
#pragma unroll
    for (int p = 0; p < 4; p++) {
        float lo0, hi0, lo1, hi1, lo2, hi2, lo3, hi3;
        upk2(lo0, hi0, acc2[p][0]); upk2(lo1, hi1, acc2[p][1]);
        upk2(lo2, hi2, acc2[p][2]); upk2(lo3, hi3, acc2[p][3]);
        int o0 = obase + ot * 8 + 2 * p;
        float b0 = bias[o0], b1 = bias[o0 + 1];
        size_t base0 = (((size_t)img * O + o0) * H + y) * W + x;
        size_t base1 = base0 + (size_t)H * W;
        float4 v0 = { lo0 + b0, lo1 + b0, lo2 + b0, lo3 + b0 };
        float4 v1 = { hi0 + b1, hi1 + b1, hi2 + b1, hi3 + b1 };
        *reinterpret_cast<float4*>(out + base0) = v0;
        *reinterpret_cast<float4*>(out + base1) = v1;
    }
}

// ---------------- conv1x1 ----------------
template<int NC>
__global__ void __launch_bounds__(256) conv1x1_k(
    const float* __restrict__ in, const float* __restrict__ wt,
    const float* __restrict__ bias, float* __restrict__ out, int C, int O, int lhw)
{
    __shared__ __align__(16) float s_x[NC * 128];
    __shared__ float s_w1[NC * 64];
    const int tid = threadIdx.x, ot = tid >> 5, pt = tid & 31;
    const int obase = blockIdx.x * 64, pbase = blockIdx.y * 128;
    const int hwm = (1 << lhw) - 1;
    float acc[8][4];
#pragma unroll
    for (int a = 0; a < 8; a++) { acc[a][0]=acc[a][1]=acc[a][2]=acc[a][3]=0.f; }

    for (int c0 = 0; c0 < C; c0 += NC) {
        const int cl = (C - c0 < NC) ? (C - c0) : NC;
        __syncthreads();
        for (int idx = tid; idx < cl * 128; idx += 256) {
            int cc = idx >> 7, i = idx & 127;
            int p = pbase + i, b = p >> lhw, hw = p & hwm;
            s_x[idx] = in[(((size_t)b * C + c0 + cc) << lhw) + hw];
        }
        for (int idx = tid; idx < cl * 64; idx += 256) {
            int cc = idx >> 6, o = idx & 63;
            s_w1[idx] = wt[(size_t)(c0 + cc) * O + obase + o];
        }
        __syncthreads();
        for (int cc = 0; cc < cl; cc++) {
            float4 xv = *reinterpret_cast<const float4*>(&s_x[cc * 128 + pt * 4]);
#pragma unroll
            for (int oo = 0; oo < 8; oo++) {
                float w = s_w1[cc * 64 + oo * 8 + ot];
                acc[oo][0] += w * xv.x; acc[oo][1] += w * xv.y;
                acc[oo][2] += w * xv.z; acc[oo][3] += w * xv.w;
            }
        }
    }
    int p = pbase + pt * 4, b = p >> lhw, hw = p & hwm;
#pragma unroll
    for (int oo = 0; oo < 8; oo++) {
        int o = obase + oo * 8 + ot;
        float bb = bias[o];
        float4 v = { acc[oo][0] + bb, acc[oo][1] + bb, acc[oo][2] + bb, acc[oo][3] + bb };
        *reinterpret_cast<float4*>(out + (((size_t)b * O + o) << lhw) + hw) = v;
    }
}

// ---------------- avgpool 2x2 (+res) ----------------
__global__ void pool_k(const float* __restrict__ in, const float* __restrict__ res,
                       float* __restrict__ out, int total, int OH, int OW)
{
    int idx = blockIdx.x * blockDim.x + threadIdx.x;
    if (idx >= total) return;
    int ow = idx % OW, t = idx / OW, oh = t % OH, bc = t / OH;
    int IW = OW * 2;
    size_t base = (((size_t)bc * (OH * 2)) + oh * 2) * IW + ow * 2;
    float v = 0.25f * (in[base] + in[base + 1] + in[base + IW] + in[base + IW + 1]);
    if (res) v += res[idx];
    out[idx] = v;
}

// ---------------- VQ support ----------------
__global__ void xnorm_k(const float* __restrict__ h, int lhw, int N) {
    int n = blockIdx.x * blockDim.x + threadIdx.x;
    if (n >= N) return;
    int b = n >> lhw, hw = n & ((1 << lhw) - 1);
    const float* p = h + (((size_t)b * 256) << lhw) + hw;
    const size_t st = (size_t)1 << lhw;
    float s = 0.f;
#pragma unroll 8
    for (int c = 0; c < 256; c++) { float v = p[(size_t)c * st]; s += v * v; }
    g_xnorm[n] = s;
}

__global__ void vq_finish_k(int HW, int C, int do_hist) {
    __shared__ float red[256];
    int b = blockIdx.x;
    float s = 0.f;
    for (int hw = threadIdx.x; hw < HW; hw += 256) {
        int n = b * HW + hw;
        float2 c0 = g_cand[(size_t)n * 16];
        float bv = c0.x; int bi = __float_as_int(c0.y);
#pragma unroll
        for (int t = 1; t < 16; t++) {
            float2 ct = g_cand[(size_t)n * 16 + t];
            if (ct.x > bv) { bv = ct.x; bi = __float_as_int(ct.y); }
        }
        s += g_xnorm[n] - 2.f * bv;
        if (do_hist) atomicAdd(&g_hist[bi], 1);
    }
    red[threadIdx.x] = s; __syncthreads();
    for (int st = 128; st > 0; st >>= 1) {
        if (threadIdx.x < st) red[threadIdx.x] += red[threadIdx.x + st];
        __syncthreads();
    }
    if (threadIdx.x == 0) g_qloss[b] += 0.5f * red[0] / ((float)HW * (float)C);
}

__global__ void ppl_k(float* __restrict__ dout, int N) {
    __shared__ float red[256];
    float s = 0.f;
    for (int k = threadIdx.x; k < 1024; k += 256) {
        float p = (float)g_hist[k] / (float)N;
        s += p * logf(p + 1e-10f);
    }
    red[threadIdx.x] = s; __syncthreads();
    for (int st = 128; st > 0; st >>= 1) {
        if (threadIdx.x < st) red[threadIdx.x] += red[threadIdx.x + st];
        __syncthreads();
    }
    if (threadIdx.x == 0) dout[128] = expf(-red[0]);
}

// ---------------- head ----------------
__global__ void hf_k(const float* __restrict__ h) {
    int idx = blockIdx.x * blockDim.x + threadIdx.x;
    if (idx >= 64 * 256) return;
    const float* p = h + (size_t)idx * 64;
    float s = 0.f;
#pragma unroll 8
    for (int i = 0; i < 64; i++) s += fmaxf(p[i], 0.f);
    g_hf[idx] = s;
}

__global__ void final_k(const int* __restrict__ y, const float* __restrict__ lin_b,
                        float* __restrict__ dout) {
    __shared__ float red[256];
    int b = blockIdx.x, c = threadIdx.x;
    float v = g_hf[b * 256 + c];
    red[c] = v * g_swlin[c] + v * g_swemb[(size_t)y[b] * 256 + c];
    __syncthreads();
    for (int st = 128; st > 0; st >>= 1) {
        if (c < st) red[c] += red[c + st];
        __syncthreads();
    }
    if (c == 0) { dout[b] = red[0] + lin_b[0]; dout[64 + b] = g_qloss[b]; }
}

// ---------------- host ----------------
#define SYMF(x) ([]{ void* p=nullptr; cudaGetSymbolAddress(&p, x); return (float*)p; }())
#define SYMB(x) ([]{ void* p=nullptr; cudaGetSymbolAddress(&p, x); return (__nv_bfloat16*)p; }())

extern "C" void kernel_launch(void* const* d_in, const int* in_sizes, int n_in,
                              void* d_out, int out_size) {
    (void)in_sizes; (void)n_in; (void)out_size;
    const float* x      = (const float*)d_in[0];
    const int*   y      = (const int*)d_in[1];
    const float* w_raw[12] = {
        (const float*)d_in[2],  (const float*)d_in[4],  (const float*)d_in[6],
        (const float*)d_in[8],  (const float*)d_in[10], (const float*)d_in[12],
        (const float*)d_in[14], (const float*)d_in[16], (const float*)d_in[18],
        (const float*)d_in[20], (const float*)d_in[26], (const float*)d_in[28] };
    const float* b0_b1 = (const float*)d_in[3],  *b0_b2 = (const float*)d_in[5];
    const float* b0_bsc= (const float*)d_in[7],  *b1_b1 = (const float*)d_in[9];
    const float* b1_b2 = (const float*)d_in[11], *b1_bsc= (const float*)d_in[13];
    const float* b2_b1 = (const float*)d_in[15], *b2_b2 = (const float*)d_in[17];
    const float* b3_b1 = (const float*)d_in[19], *b3_b2 = (const float*)d_in[21];
    const float* cb0 = (const float*)d_in[22], *cb1 = (const float*)d_in[23];
    const float* cb2 = (const float*)d_in[24], *cb3 = (const float*)d_in[25];
    const float* lin_b = (const float*)d_in[27];
    float* dout = (float*)d_out;

    float *A = SYMF(g_A), *B = SYMF(g_B), *H0 = SYMF(g_H0), *SC = SYMF(g_SC);
    float *T8 = SYMF(g_T8), *H1 = SYMF(g_H1), *H2 = SYMF(g_H2), *H3 = SYMF(g_H3);
    float *PX = SYMF(g_PX);
    float *sw0 = SYMF(g_sw0), *sw2 = SYMF(g_sw2), *sw5 = SYMF(g_sw5);
    float *swlin = SYMF(g_swlin), *swemb = SYMF(g_swemb);
    float *en = SYMF(g_enorm4);
    __nv_bfloat16 *wbh = SYMB(g_wbh), *wbl = SYMB(g_wbl);
    __nv_bfloat16 *cbh = SYMB(g_cbh), *cbl = SYMB(g_cbl);

    const size_t WSZ = 589824u;
    SnArgs sa;
    sa.d[0]  = SnDesc{ w_raw[0],  sw0,  nullptr, nullptr, 256, 27,   1 };
    sa.d[1]  = SnDesc{ w_raw[1],  nullptr, wbh + 0*WSZ, wbl + 0*WSZ, 256, 2304, 2 };
    sa.d[2]  = SnDesc{ w_raw[2],  sw2,  nullptr, nullptr, 256, 3,    1 };
    sa.d[3]  = SnDesc{ w_raw[3],  nullptr, wbh + 1*WSZ, wbl + 1*WSZ, 256, 2304, 2 };
    sa.d[4]  = SnDesc{ w_raw[4],  nullptr, wbh + 2*WSZ, wbl + 2*WSZ, 256, 2304, 2 };
    sa.d[5]  = SnDesc{ w_raw[5],  sw5,  nullptr, nullptr, 256, 256,  1 };
    sa.d[6]  = SnDesc{ w_raw[6],  nullptr, wbh + 3*WSZ, wbl + 3*WSZ, 256, 2304, 2 };
    sa.d[7]  = SnDesc{ w_raw[7],  nullptr, wbh + 4*WSZ, wbl + 4*WSZ, 256, 2304, 2 };
    sa.d[8]  = SnDesc{ w_raw[8],  nullptr, wbh + 5*WSZ, wbl + 5*WSZ, 256, 2304, 2 };
    sa.d[9]  = SnDesc{ w_raw[9],  nullptr, wbh + 6*WSZ, wbl + 6*WSZ, 256, 2304, 2 };
    sa.d[10] = SnDesc{ w_raw[10], swlin, nullptr, nullptr, 1,   256, 0 };
    sa.d[11] = SnDesc{ w_raw[11], swemb, nullptr, nullptr, 100, 256, 0 };

    cudaFuncSetAttribute(conv_mma_k<4,32,1,64>, cudaFuncAttributeMaxDynamicSharedMemorySize, 74880);
    cudaFuncSetAttribute(conv_mma_k<8,16,1,64>, cudaFuncAttributeMaxDynamicSharedMemorySize, 72576);

    static cudaStream_t s1 = nullptr, s2 = nullptr;
    static cudaEvent_t evFork, evFin, evWall, evSC0, evH0, evSC1, evH1, evH2, evH3, evVQ;
    if (!s1) {
        cudaStreamCreateWithFlags(&s1, cudaStreamNonBlocking);
        cudaStreamCreateWithFlags(&s2, cudaStreamNonBlocking);
        cudaEventCreateWithFlags(&evFork, cudaEventDisableTiming);
        cudaEventCreateWithFlags(&evFin,  cudaEventDisableTiming);
        cudaEventCreateWithFlags(&evWall, cudaEventDisableTiming);
        cudaEventCreateWithFlags(&evSC0,  cudaEventDisableTiming);
        cudaEventCreateWithFlags(&evH0,   cudaEventDisableTiming);
        cudaEventCreateWithFlags(&evSC1,  cudaEventDisableTiming);
        cudaEventCreateWithFlags(&evH1,   cudaEventDisableTiming);
        cudaEventCreateWithFlags(&evH2,   cudaEventDisableTiming);
        cudaEventCreateWithFlags(&evH3,   cudaEventDisableTiming);
        cudaEventCreateWithFlags(&evVQ,   cudaEventDisableTiming);
    }
    cudaStream_t s0 = 0;

    // fork
    cudaEventRecord(evFork, s0);
    cudaStreamWaitEvent(s1, evFork, 0);
    cudaStreamWaitEvent(s2, evFork, 0);

    // s1: VQ prep
    init_zero_k<<<4, 256, 0, s1>>>();
    enorm_k<<<4, 256, 0, s1>>>(cb0, en + 0*1024);
    enorm_k<<<4, 256, 0, s1>>>(cb1, en + 1*1024);
    enorm_k<<<4, 256, 0, s1>>>(cb2, en + 2*1024);
    enorm_k<<<4, 256, 0, s1>>>(cb3, en + 3*1024);
    cbt_k<<<1024, 256, 0, s1>>>(cb0, cbh + 0*262144u, cbl + 0*262144u);
    cbt_k<<<1024, 256, 0, s1>>>(cb1, cbh + 1*262144u, cbl + 1*262144u);
    cbt_k<<<1024, 256, 0, s1>>>(cb2, cbh + 2*262144u, cbl + 2*262144u);
    cbt_k<<<1024, 256, 0, s1>>>(cb3, cbh + 3*262144u, cbl + 3*262144u);

    // s2: x pooling
    pool_k<<<192, 256, 0, s2>>>(x, nullptr, PX, 64*3*16*16, 16, 16);

    // s0: spectral norm (parallel); slot 0 scaled first so conv0 starts early
    sn_col_k<<<dim3(12, 8), 256, 0, s0>>>(sa);
    sn_row_k<<<dim3(12, 8), 256, 0, s0>>>(sa);
    sn_fin_k<<<1, 32, 0, s0>>>();
    cudaEventRecord(evFin, s0);
    sn_scale_k<<<dim3(1, 1), 256, 0, s0>>>(sa, 0);
    conv3x3_k<4,32,1,3><<<dim3(4, 8, 64), 256, 0, s0>>>(x, sw0, b0_b1, A, 3, 256, 32, 32, 0);

    // s2: scale remaining slots concurrently with conv0
    cudaStreamWaitEvent(s2, evFin, 0);
    sn_scale_k<<<dim3(11, 64), 256, 0, s2>>>(sa, 1);
    cudaEventRecord(evWall, s2);
    conv1x1_k<16><<<dim3(4, 128), 256, 0, s2>>>(PX, sw2, b0_bsc, SC, 3, 256, 8);
    cudaEventRecord(evSC0, s2);

    // s0: block-0 main path
    cudaStreamWaitEvent(s0, evWall, 0);
    conv_mma_k<4,32,1,64><<<dim3(4, 512), 256, 74880, s0>>>(A, wbh + 0*WSZ, wbl + 0*WSZ, b0_b2, nullptr, B, 256, 256, 32, 1);
    cudaStreamWaitEvent(s0, evSC0, 0);
    pool_k<<<16384, 256, 0, s0>>>(B, SC, H0, 64*256*16*16, 16, 16);
    cudaEventRecord(evH0, s0);

    // s1: VQ0 (HW=256)
    cudaStreamWaitEvent(s1, evH0, 0);
    xnorm_k<<<64, 256, 0, s1>>>(H0, 8, 16384);
    vq_mma_k<<<dim3(16, 128), 256, 0, s1>>>(H0, cbh + 0*262144u, cbl + 0*262144u, en + 0*1024, 256, 8);
    vq_finish_k<<<64, 256, 0, s1>>>(256, 256, 0);

    // s2: block-1 shortcut
    cudaStreamWaitEvent(s2, evH0, 0);
    pool_k<<<4096, 256, 0, s2>>>(H0, nullptr, T8, 64*256*8*8, 8, 8);
    conv1x1_k<16><<<dim3(4, 32), 256, 0, s2>>>(T8, sw5, b1_bsc, SC, 256, 256, 6);
    cudaEventRecord(evSC1, s2);

    // s0: block-1 main path
    conv_mma_k<8,16,1,64><<<dim3(4, 128), 256, 72576, s0>>>(H0, wbh + 1*WSZ, wbl + 1*WSZ, b1_b1, nullptr, A, 256, 256, 16, 1);
    conv_mma_k<8,16,1,64><<<dim3(4, 128), 256, 72576, s0>>>(A,  wbh + 2*WSZ, wbl + 2*WSZ, b1_b2, nullptr, B, 256, 256, 16, 1);
    cudaStreamWaitEvent(s0, evSC1, 0);
    pool_k<<<4096, 256, 0, s0>>>(B, SC, H1, 64*256*8*8, 8, 8);
    cudaEventRecord(evH1, s0);

    // s1: VQ1
    cudaStreamWaitEvent(s1, evH1, 0);
    xnorm_k<<<16, 256, 0, s1>>>(H1, 6, 4096);
    vq_mma_k<<<dim3(16, 32), 256, 0, s1>>>(H1, cbh + 1*262144u, cbl + 1*262144u, en + 1*1024, 256, 6);
    vq_finish_k<<<64, 256, 0, s1>>>(64, 256, 0);

    // s0: block 2 (NOC=32 -> 256 CTAs, smem < 48KB)
    conv_mma_k<8,8,2,32><<<dim3(8, 32), 256, 46848, s0>>>(H1, wbh + 3*WSZ, wbl + 3*WSZ, b2_b1, nullptr, A,  256, 256, 8, 1);
    conv_mma_k<8,8,2,32><<<dim3(8, 32), 256, 46848, s0>>>(A,  wbh + 4*WSZ, wbl + 4*WSZ, b2_b2, H1,      H2, 256, 256, 8, 1);
    cudaEventRecord(evH2, s0);

    // s1: VQ2
    cudaStreamWaitEvent(s1, evH2, 0);
    xnorm_k<<<16, 256, 0, s1>>>(H2, 6, 4096);
    vq_mma_k<<<dim3(16, 32), 256, 0, s1>>>(H2, cbh + 2*262144u, cbl + 2*262144u, en + 2*1024, 256, 6);
    vq_finish_k<<<64, 256, 0, s1>>>(64, 256, 0);

    // s0: block 3
    conv_mma_k<8,8,2,32><<<dim3(8, 32), 256, 46848, s0>>>(H2, wbh + 5*WSZ, wbl + 5*WSZ, b3_b1, nullptr, A,  256, 256, 8, 1);
    conv_mma_k<8,8,2,32><<<dim3(8, 32), 256, 46848, s0>>>(A,  wbh + 6*WSZ, wbl + 6*WSZ, b3_b2, H2,      H3, 256, 256, 8, 1);
    cudaEventRecord(evH3, s0);

    // s1: VQ3 (+hist)
    cudaStreamWaitEvent(s1, evH3, 0);
    xnorm_k<<<16, 256, 0, s1>>>(H3, 6, 4096);
    vq_mma_k<<<dim3(16, 32), 256, 0, s1>>>(H3, cbh + 3*262144u, cbl + 3*262144u, en + 3*1024, 256, 6);
    vq_finish_k<<<64, 256, 0, s1>>>(64, 256, 1);
    cudaEventRecord(evVQ, s1);

    // s0: head
    hf_k<<<64, 256, 0, s0>>>(H3);
    cudaStreamWaitEvent(s0, evVQ, 0);
    final_k<<<64, 256, 0, s0>>>(y, lin_b, dout);
    ppl_k<<<1, 256, 0, s0>>>(dout, 4096);
}

// round 17
// speedup vs baseline: 1.0304x; 1.0304x over previous
#include <cuda_runtime.h>
#include <cuda_bf16.h>
#include <math.h>

typedef unsigned long long ull;
typedef unsigned int u32;

// ---------------- mma helpers ----------------
#define LDSM_X4(r0,r1,r2,r3,addr) \
  asm volatile("ldmatrix.sync.aligned.m8n8.x4.shared.b16 {%0,%1,%2,%3},[%4];" \
    : "=r"(r0),"=r"(r1),"=r"(r2),"=r"(r3) : "r"(addr))

#define MMA_BF16(d,a0,a1,a2,a3,b0,b1) \
  asm volatile("mma.sync.aligned.m16n8k16.row.col.f32.bf16.bf16.f32 " \
    "{%0,%1,%2,%3},{%4,%5,%6,%7},{%8,%9},{%0,%1,%2,%3};" \
    : "+f"((d)[0]),"+f"((d)[1]),"+f"((d)[2]),"+f"((d)[3]) \
    : "r"(a0),"r"(a1),"r"(a2),"r"(a3),"r"(b0),"r"(b1))

// ---------------- static device scratch ----------------
__device__ float g_A[64u*256u*32u*32u];
__device__ float g_B[64u*256u*32u*32u];
__device__ float g_H0[64u*256u*16u*16u];
__device__ float g_SC[64u*256u*16u*16u];
__device__ float g_T8[64u*256u*8u*8u];
__device__ float g_H1[64u*256u*8u*8u];
__device__ float g_H2[64u*256u*8u*8u];
__device__ float g_H3[64u*256u*8u*8u];
__device__ float g_PX[64u*3u*16u*16u];

__device__ float g_sw0[6912];
__device__ float g_sw2[768];
__device__ float g_sw5[65536];
__device__ float g_swlin[256];
__device__ float g_swemb[25600];

__device__ __nv_bfloat16 g_wbh[7u*589824u];
__device__ __nv_bfloat16 g_wbl[7u*589824u];
__device__ __nv_bfloat16 g_cbh[4u*262144u];
__device__ __nv_bfloat16 g_cbl[4u*262144u];

__device__ float g_sigma[12];
__device__ float g_sv[12*2304];
__device__ float g_p1[96];
__device__ float g_p2[96];
__device__ float g_enorm4[4*1024];
__device__ float2 g_cand[16384*16];
__device__ float g_xnorm[16384];
__device__ float g_qloss[64];
__device__ int   g_hist[1024];
__device__ float g_hf[64*256];

// ---------------- spectral norm (parallel, deterministic) ----------------
struct SnDesc { const float* w; float* out; __nv_bfloat16* oh; __nv_bfloat16* ol;
                int O; int R; int mode; };
struct SnArgs { SnDesc d[12]; };

__global__ void init_zero_k() {
    int i = blockIdx.x * blockDim.x + threadIdx.x;
    if (i < 1024) g_hist[i] = 0;
    if (i < 64)   g_qloss[i] = 0.f;
}

__global__ void sn_col_k(SnArgs a) {
    __shared__ float red[256];
    const int w = blockIdx.x, seg = blockIdx.y, tid = threadIdx.x;
    const SnDesc d = a.d[w];
    const int O = d.O, R = d.R;
    const int Rper = (R + 7) / 8;
    const int j0 = seg * Rper;
    const int j1 = (j0 + Rper < R) ? (j0 + Rper) : R;
    const float is = rsqrtf((float)O);
    float loc = 0.f;
    for (int j = j0 + tid; j < j1; j += 256) {
        float s = 0.f;
#pragma unroll 4
        for (int i = 0; i < O; i++) s += d.w[(size_t)i * R + j];
        s *= is;
        g_sv[w * 2304 + j] = s;
        loc += s * s;
    }
    red[tid] = loc; __syncthreads();
    for (int s = 128; s > 0; s >>= 1) { if (tid < s) red[tid] += red[tid + s]; __syncthreads(); }
    if (tid == 0) g_p1[w * 8 + seg] = red[0];
}

__global__ void sn_row_k(SnArgs a) {
    __shared__ float red[256];
    const int w = blockIdx.x, seg = blockIdx.y, tid = threadIdx.x;
    const int wid = tid >> 5, lane = tid & 31;
    const SnDesc d = a.d[w];
    const int O = d.O, R = d.R;
    float s1 = 0.f;
#pragma unroll
    for (int s = 0; s < 8; s++) s1 += g_p1[w * 8 + s];
    const float fv = 1.f / (sqrtf(s1) + 1e-8f);
    const int Oper = (O + 7) / 8;
    const int i0 = seg * Oper;
    const int i1 = (i0 + Oper < O) ? (i0 + Oper) : O;
    const float* sv = &g_sv[w * 2304];
    float loc = 0.f;
    for (int i = i0 + wid; i < i1; i += 8) {
        float t = 0.f;
        const float* row = d.w + (size_t)i * R;
        for (int j = lane; j < R; j += 32) t += row[j] * sv[j];
#pragma unroll
        for (int off = 16; off; off >>= 1) t += __shfl_xor_sync(0xffffffffu, t, off);
        t *= fv;
        if (lane == 0) loc += t * t;
    }
    red[tid] = loc; __syncthreads();
    for (int s = 128; s > 0; s >>= 1) { if (tid < s) red[tid] += red[tid + s]; __syncthreads(); }
    if (tid == 0) g_p2[w * 8 + seg] = red[0];
}

__global__ void sn_fin_k() {
    int w = threadIdx.x;
    if (w >= 12) return;
    float s = 0.f;
#pragma unroll
    for (int i = 0; i < 8; i++) s += g_p2[w * 8 + i];
    g_sigma[w] = s / (sqrtf(s) + 1e-8f);
}

__global__ void sn_scale_k(SnArgs a, int base) {
    const int w = base + blockIdx.x;
    const SnDesc d = a.d[w];
    const float inv = 1.f / g_sigma[w];
    const int n = d.O * d.R, stride = gridDim.y * blockDim.x;
    for (int e = blockIdx.y * blockDim.x + threadIdx.x; e < n; e += stride) {
        float v = d.w[e] * inv;
        if (d.mode == 0) {
            d.out[e] = v;
        } else if (d.mode == 1) {
            int o = e / d.R, rr = e % d.R;
            d.out[(size_t)rr * d.O + o] = v;
        } else {
            int o = e / d.R, rem = e % d.R;
            int c = rem / 9, tap = rem % 9;
            size_t oi = ((size_t)tap * d.O + o) * (d.R / 9) + c;
            __nv_bfloat16 h = __float2bfloat16(v);
            d.oh[oi] = h;
            d.ol[oi] = __float2bfloat16(v - __bfloat162float(h));
        }
    }
}

__global__ void enorm_k(const float* __restrict__ cb, float* __restrict__ en) {
    int k = blockIdx.x * blockDim.x + threadIdx.x;
    if (k >= 1024) return;
    float s = 0.f;
#pragma unroll 4
    for (int c = 0; c < 256; c++) { float v = cb[(size_t)c * 1024 + k]; s += v * v; }
    en[k] = s;
}

__global__ void cbt_k(const float* __restrict__ cb,
                      __nv_bfloat16* __restrict__ oh, __nv_bfloat16* __restrict__ ol) {
    int idx = blockIdx.x * 256 + threadIdx.x;
    int code = idx & 1023, c = idx >> 10;
    float v = cb[(size_t)c * 1024 + code];
    __nv_bfloat16 h = __float2bfloat16(v);
    oh[(size_t)code * 256 + c] = h;
    ol[(size_t)code * 256 + c] = __float2bfloat16(v - __bfloat162float(h));
}

// ---------------- mma conv3x3 (C multiple of 16, W==TW), NOC oc per block ----------------
template<int TH, int TW, int G, int NOC>
__global__ void __launch_bounds__(256) conv_mma_k(
    const float* __restrict__ in, const __nv_bfloat16* __restrict__ wh,
    const __nv_bfloat16* __restrict__ wl, const float* __restrict__ bias,
    const float* __restrict__ res, float* __restrict__ out,
    int C, int O, int H, int relu_in)
{
    constexpr int PH = TH + 2, PWW = TW + 2, NPX = G * PH * PWW, AST = 24;
    constexpr int W = TW;
    constexpr int NT = NOC / 16;
    constexpr int NA = NOC / 8;
    extern __shared__ __align__(16) char smraw[];
    __nv_bfloat16* sAh = (__nv_bfloat16*)smraw;
    __nv_bfloat16* sAl = sAh + NPX * AST;
    __nv_bfloat16* sBh = sAl + NPX * AST;
    __nv_bfloat16* sBl = sBh + 9 * NOC * AST;

    const int tid = threadIdx.x, wi = tid >> 5, lane = tid & 31;
    const int obase = blockIdx.x * NOC;
    const int TPI = H / TH;
    const int tileY = (G == 1) ? (blockIdx.y % TPI) : 0;
    const int imgb  = (G == 1) ? (blockIdx.y / TPI) : blockIdx.y * G;

    const int p = wi * 16 + (lane & 15);
    const int fg = p / (TH * TW), fr = p % (TH * TW), fpy = fr / TW, fpx = fr % TW;
    const u32 aRow = (u32)((fg * PH + fpy) * PWW + fpx);
    const u32 aH = (u32)__cvta_generic_to_shared(sAh) + (aRow * AST + (lane >> 4) * 8) * 2;
    const u32 aL = (u32)__cvta_generic_to_shared(sAl) + (aRow * AST + (lane >> 4) * 8) * 2;
    const int l8 = lane & 7, seg = lane >> 3;
    const u32 bRow = (u32)((((seg >> 1) * 8 + l8) * AST + (seg & 1) * 8) * 2);
    const u32 bH0 = (u32)__cvta_generic_to_shared(sBh) + bRow;
    const u32 bL0 = (u32)__cvta_generic_to_shared(sBl) + bRow;

    float acc[NA][4];
#pragma unroll
    for (int t = 0; t < NA; t++) { acc[t][0]=acc[t][1]=acc[t][2]=acc[t][3]=0.f; }

    const int nch = C / 16;
    for (int ck = 0; ck < nch; ck++) {
        const int c0 = ck * 16;
        __syncthreads();
        for (int idx = tid; idx < NPX * 16; idx += 256) {
            int ch = idx / NPX, r = idx % NPX;
            int gg = r / (PH * PWW), r2 = r % (PH * PWW);
            int py = r2 / PWW, pxx = r2 % PWW;
            int gy = tileY * TH + py - 1, gx = pxx - 1;
            float v = 0.f;
            if ((unsigned)gy < (unsigned)H && (unsigned)gx < (unsigned)W)
                v = in[(((size_t)(imgb + gg) * C + c0 + ch) * H + gy) * W + gx];
            if (relu_in) v = fmaxf(v, 0.f);
            __nv_bfloat16 h = __float2bfloat16(v);
            sAh[r * AST + ch] = h;
            sAl[r * AST + ch] = __float2bfloat16(v - __bfloat162float(h));
        }
        for (int idx = tid; idx < 9 * NOC * 2; idx += 256) {
            int half = idx & 1, o = (idx >> 1) % NOC, tap = (idx >> 1) / NOC;
            size_t ga = ((size_t)(tap * O + obase + o)) * C + c0 + half * 8;
            int so = (tap * NOC + o) * AST + half * 8;
            *(uint4*)(sBh + so) = *(const uint4*)(wh + ga);
            *(uint4*)(sBl + so) = *(const uint4*)(wl + ga);
        }
        __syncthreads();

#pragma unroll
        for (int tap = 0; tap < 9; tap++) {
            const int dy = tap / 3, dx = tap % 3;
            const u32 sh = (u32)((dy * PWW + dx) * AST * 2);
            u32 ah0,ah1,ah2,ah3, al0,al1,al2,al3;
            LDSM_X4(ah0,ah1,ah2,ah3, aH + sh);
            LDSM_X4(al0,al1,al2,al3, aL + sh);
#pragma unroll
            for (int tg = 0; tg < NT; tg++) {
                const u32 off = (u32)((tap * NOC + tg * 16) * AST * 2);
                u32 bh0,bh1,bh2,bh3, bl0,bl1,bl2,bl3;
                LDSM_X4(bh0,bh1,bh2,bh3, bH0 + off);
                LDSM_X4(bl0,bl1,bl2,bl3, bL0 + off);
                MMA_BF16(acc[2*tg],   ah0,ah1,ah2,ah3, bh0,bh1);
                MMA_BF16(acc[2*tg+1], ah0,ah1,ah2,ah3, bh2,bh3);
                MMA_BF16(acc[2*tg],   ah0,ah1,ah2,ah3, bl0,bl1);
                MMA_BF16(acc[2*tg+1], ah0,ah1,ah2,ah3, bl2,bl3);
                MMA_BF16(acc[2*tg],   al0,al1,al2,al3, bh0,bh1);
                MMA_BF16(acc[2*tg+1], al0,al1,al2,al3, bh2,bh3);
            }
        }
    }

    const int q = lane >> 2, cp = (lane & 3) * 2;
#pragma unroll
    for (int rI = 0; rI < 2; rI++) {
        int pp = wi * 16 + q + rI * 8;
        int gg = pp / (TH * TW), r = pp % (TH * TW), py = r / TW, px = r % TW;
        int img = imgb + gg, y = tileY * TH + py;
        size_t pixoff = (((size_t)img * O) * H + y) * W + px;
#pragma unroll
        for (int t = 0; t < NA; t++) {
            int oc = obase + t * 8 + cp;
            size_t a0 = pixoff + (size_t)oc * H * W;
            size_t a1 = a0 + (size_t)H * W;
            float v0 = acc[t][rI * 2 + 0] + bias[oc];
            float v1 = acc[t][rI * 2 + 1] + bias[oc + 1];
            if (res) { v0 += res[a0]; v1 += res[a1]; }
            out[a0] = v0; out[a1] = v1;
        }
    }
}

// ---------------- mma VQ ----------------
__global__ void __launch_bounds__(256) vq_mma_k(
    const float* __restrict__ h, const __nv_bfloat16* __restrict__ cbh,
    const __nv_bfloat16* __restrict__ cbl, const float* __restrict__ enorm,
    int C, int lhw)
{
    constexpr int AST = 24;
    __shared__ __align__(16) __nv_bfloat16 sAh[128 * AST];
    __shared__ __align__(16) __nv_bfloat16 sAl[128 * AST];
    __shared__ __align__(16) __nv_bfloat16 sBh[64 * AST];
    __shared__ __align__(16) __nv_bfloat16 sBl[64 * AST];

    const int tid = threadIdx.x, wi = tid >> 5, lane = tid & 31;
    const int ktile = blockIdx.x, pbase = blockIdx.y * 128;
    const int hwm = (1 << lhw) - 1;

    const int p = wi * 16 + (lane & 15);
    const u32 aH = (u32)__cvta_generic_to_shared(sAh) + (p * AST + (lane >> 4) * 8) * 2;
    const u32 aL = (u32)__cvta_generic_to_shared(sAl) + (p * AST + (lane >> 4) * 8) * 2;
    const int l8 = lane & 7, seg = lane >> 3;
    const u32 bRow = (u32)((((seg >> 1) * 8 + l8) * AST + (seg & 1) * 8) * 2);
    const u32 bH0 = (u32)__cvta_generic_to_shared(sBh) + bRow;
    const u32 bL0 = (u32)__cvta_generic_to_shared(sBl) + bRow;

    float acc[8][4];
#pragma unroll
    for (int t = 0; t < 8; t++) { acc[t][0]=acc[t][1]=acc[t][2]=acc[t][3]=0.f; }

    for (int ck = 0; ck < C / 16; ck++) {
        const int c0 = ck * 16;
        __syncthreads();
        for (int idx = tid; idx < 512; idx += 256) {
            int ch = idx >> 5, grp = idx & 31;
            int i = grp * 4;
            int pg = pbase + i, b = pg >> lhw, hw = pg & hwm;
            float4 v = *(const float4*)(h + (((size_t)b * C + c0 + ch) << lhw) + hw);
            float vs[4] = { v.x, v.y, v.z, v.w };
#pragma unroll
            for (int j = 0; j < 4; j++) {
                __nv_bfloat16 hv = __float2bfloat16(vs[j]);
                sAh[(i + j) * AST + ch] = hv;
                sAl[(i + j) * AST + ch] = __float2bfloat16(vs[j] - __bfloat162float(hv));
            }
        }
        for (int idx = tid; idx < 128; idx += 256) {
            int half = idx & 1, code = idx >> 1;
            size_t ga = (size_t)(ktile * 64 + code) * 256 + c0 + half * 8;
            int so = code * AST + half * 8;
            *(uint4*)(sBh + so) = *(const uint4*)(cbh + ga);
            *(uint4*)(sBl + so) = *(const uint4*)(cbl + ga);
        }
        __syncthreads();

        u32 ah0,ah1,ah2,ah3, al0,al1,al2,al3;
        LDSM_X4(ah0,ah1,ah2,ah3, aH);
        LDSM_X4(al0,al1,al2,al3, aL);
#pragma unroll
        for (int tg = 0; tg < 4; tg++) {
            const u32 off = (u32)(tg * 16 * AST * 2);
            u32 bh0,bh1,bh2,bh3, bl0,bl1,bl2,bl3;
            LDSM_X4(bh0,bh1,bh2,bh3, bH0 + off);
            LDSM_X4(bl0,bl1,bl2,bl3, bL0 + off);
            MMA_BF16(acc[2*tg],   ah0,ah1,ah2,ah3, bh0,bh1);
            MMA_BF16(acc[2*tg+1], ah0,ah1,ah2,ah3, bh2,bh3);
            MMA_BF16(acc[2*tg],   ah0,ah1,ah2,ah3, bl0,bl1);
            MMA_BF16(acc[2*tg+1], ah0,ah1,ah2,ah3, bl2,bl3);
            MMA_BF16(acc[2*tg],   al0,al1,al2,al3, bh0,bh1);
            MMA_BF16(acc[2*tg+1], al0,al1,al2,al3, bh2,bh3);
        }
    }

    const int q = lane >> 2, cp = (lane & 3) * 2;
#pragma unroll
    for (int rI = 0; rI < 2; rI++) {
        float bv = -1e30f; int bi = 0;
#pragma unroll
        for (int t = 0; t < 8; t++) {
            int code = ktile * 64 + t * 8 + cp;
            float s0 = acc[t][rI * 2 + 0] - 0.5f * enorm[code];
            float s1 = acc[t][rI * 2 + 1] - 0.5f * enorm[code + 1];
            if (s0 > bv) { bv = s0; bi = code; }
            if (s1 > bv) { bv = s1; bi = code + 1; }
        }
#pragma unroll
        for (int off = 1; off <= 2; off <<= 1) {
            float ov = __shfl_down_sync(0xffffffffu, bv, off);
            int   oi = __shfl_down_sync(0xffffffffu, bi, off);
            if (ov > bv || (ov == bv && oi < bi)) { bv = ov; bi = oi; }
        }
        if ((lane & 3) == 0) {
            int pg = pbase + wi * 16 + q + rI * 8;
            g_cand[(size_t)pg * 16 + ktile] = make_float2(bv, __int_as_float(bi));
        }
    }
}

// ---------------- scalar conv3x3 (only for C=3 first conv) ----------------
__device__ __forceinline__ ull pk2(float lo, float hi) {
    ull r; asm("mov.b64 %0,{%1,%2};" : "=l"(r) : "f"(lo), "f"(hi)); return r;
}
__device__ __forceinline__ void upk2(float& lo, float& hi, ull v) {
    asm("mov.b64 {%0,%1},%2;" : "=f"(lo), "=f"(hi) : "l"(v));
}
__device__ __forceinline__ ull fma2(ull a, ull b, ull c) {
    ull d; asm("fma.rn.f32x2 %0,%1,%2,%3;" : "=l"(d) : "l"(a), "l"(b), "l"(c)); return d;
}

template<int TH, int TW, int G, int NC>
__global__ void __launch_bounds__(256) conv3x3_k(
    const float* __restrict__ in, const float* __restrict__ wt,
    const float* __restrict__ bias, float* __restrict__ out,
    int C, int O, int H, int W, int relu_in)
{
    constexpr int PH = TH + 2, PW = TW + 4, XG = TW / 4;
    constexpr int SROW = TW + 2;
    __shared__ __align__(16) float s_in[NC * G * PH * PW];
    __shared__ __align__(16) float s_w2[NC * 576];
    const int tid = threadIdx.x, ot = tid >> 5, pt = tid & 31;
    const int g = pt / (TH * XG), r = pt % (TH * XG), row = r / XG, xg = r % XG;
    const int tilesX = W / TW;
    const int tileY = blockIdx.y / tilesX, tileX = blockIdx.y % tilesX;
    const int img = blockIdx.z * G + g, obase = blockIdx.x * 64;

    ull acc2[4][4];
#pragma unroll
    for (int p = 0; p < 4; p++)
#pragma unroll
        for (int px = 0; px < 4; px++) acc2[p][px] = 0ull;

    for (int c0 = 0; c0 < C; c0 += NC) {
        __syncthreads();
        for (int idx = tid; idx < NC * G * PH * SROW; idx += 256) {
            int cc = idx / (G * PH * SROW);
            int r3 = idx % (G * PH * SROW);
            int gg = r3 / (PH * SROW);
            int r2 = r3 % (PH * SROW);
            int py = r2 / SROW, px = r2 % SROW;
            int gy = tileY * TH + py - 1, gx = tileX * TW + px - 1;
            float v = 0.f;
            if ((unsigned)gy < (unsigned)H && (unsigned)gx < (unsigned)W)
                v = in[(((size_t)(blockIdx.z * G + gg) * C + c0 + cc) * H + gy) * W + gx];
            if (relu_in) v = fmaxf(v, 0.f);
            s_in[(cc * G + gg) * PH * PW + py * PW + px] = v;
        }
        for (int idx = tid; idx < NC * 576; idx += 256) {
            int cc = idx / 576, r2 = idx % 576;
            int k = r2 >> 6, o = r2 & 63;
            s_w2[cc * 576 + (o >> 1) * 18 + k * 2 + (o & 1)] =
                wt[((size_t)(c0 + cc) * 9 + k) * O + obase + o];
        }
        __syncthreads();

#pragma unroll 1
        for (int cc = 0; cc < NC; cc++) {
            const float* sp = &s_in[(cc * G + g) * PH * PW + row * PW + xg * 4];
            const ull* wp = (const ull*)&s_w2[cc * 576 + ot * 72];
#pragma unroll
            for (int dy = 0; dy < 3; dy++) {
                float4 v4 = *(const float4*)(sp + dy * PW);
                float2 v2 = *(const float2*)(sp + dy * PW + 4);
                ull ivb[6];
                ivb[0] = pk2(v4.x, v4.x); ivb[1] = pk2(v4.y, v4.y);
                ivb[2] = pk2(v4.z, v4.z); ivb[3] = pk2(v4.w, v4.w);
                ivb[4] = pk2(v2.x, v2.x); ivb[5] = pk2(v2.y, v2.y);
#pragma unroll
                for (int dx = 0; dx < 3; dx++) {
                    const int k = dy * 3 + dx;
#pragma unroll
                    for (int p = 0; p < 4; p++) {
                        ull w = wp[p * 9 + k];
                        acc2[p][0] = fma2(w, ivb[dx + 0], acc2[p][0]);
                        acc2[p][1] = fma2(w, ivb[dx + 1], acc2[p][1]);
                        acc2[p][2] = fma2(w, ivb[dx + 2], acc2[p][2]);
                        acc2[p][3] = fma2(w, ivb[dx + 3], acc2[p][3]);
                    }
                }
            }
        }
    }

    const int y = tileY * TH + row, x = tileX * TW + xg * 4;
#pragma unroll
    for (int p = 0; p < 4; p++) {
        float lo0, hi0, lo1, hi1, lo2, hi2, lo3, hi3;
        upk2(lo0, hi0, acc2[p][0]); upk2(lo1, hi1, acc2[p][1]);
        upk2(lo2, hi2, acc2[p][2]); upk2(lo3, hi3, acc2[p][3]);
        int o0 = obase + ot * 8 + 2 * p;
        float b0 = bias[o0], b1 = bias[o0 + 1];
        size_t base0 = (((size_t)img * O + o0) * H + y) * W + x;
        size_t base1 = base0 + (size_t)H * W;
        float4 v0 = { lo0 + b0, lo1 + b0, lo2 + b0, lo3 + b0 };
        float4 v1 = { hi0 + b1, hi1 + b1, hi2 + b1, hi3 + b1 };
        *reinterpret_cast<float4*>(out + base0) = v0;
        *reinterpret_cast<float4*>(out + base1) = v1;
    }
}

// ---------------- conv1x1 ----------------
template<int NC>
__global__ void __launch_bounds__(256) conv1x1_k(
    const float* __restrict__ in, const float* __restrict__ wt,
    const float* __restrict__ bias, float* __restrict__ out, int C, int O, int lhw)
{
    __shared__ __align__(16) float s_x[NC * 128];
    __shared__ float s_w1[NC * 64];
    const int tid = threadIdx.x, ot = tid >> 5, pt = tid & 31;
    const int obase = blockIdx.x * 64, pbase = blockIdx.y * 128;
    const int hwm = (1 << lhw) - 1;
    float acc[8][4];
#pragma unroll
    for (int a = 0; a < 8; a++) { acc[a][0]=acc[a][1]=acc[a][2]=acc[a][3]=0.f; }

    for (int c0 = 0; c0 < C; c0 += NC) {
        const int cl = (C - c0 < NC) ? (C - c0) : NC;
        __syncthreads();
        for (int idx = tid; idx < cl * 128; idx += 256) {
            int cc = idx >> 7, i = idx & 127;
            int p = pbase + i, b = p >> lhw, hw = p & hwm;
            s_x[idx] = in[(((size_t)b * C + c0 + cc) << lhw) + hw];
        }
        for (int idx = tid; idx < cl * 64; idx += 256) {
            int cc = idx >> 6, o = idx & 63;
            s_w1[idx] = wt[(size_t)(c0 + cc) * O + obase + o];
        }
        __syncthreads();
        for (int cc = 0; cc < cl; cc++) {
            float4 xv = *reinterpret_cast<const float4*>(&s_x[cc * 128 + pt * 4]);
#pragma unroll
            for (int oo = 0; oo < 8; oo++) {
                float w = s_w1[cc * 64 + oo * 8 + ot];
                acc[oo][0] += w * xv.x; acc[oo][1] += w * xv.y;
                acc[oo][2] += w * xv.z; acc[oo][3] += w * xv.w;
            }
        }
    }
    int p = pbase + pt * 4, b = p >> lhw, hw = p & hwm;
#pragma unroll
    for (int oo = 0; oo < 8; oo++) {
        int o = obase + oo * 8 + ot;
        float bb = bias[o];
        float4 v = { acc[oo][0] + bb, acc[oo][1] + bb, acc[oo][2] + bb, acc[oo][3] + bb };
        *reinterpret_cast<float4*>(out + (((size_t)b * O + o) << lhw) + hw) = v;
    }
}

// ---------------- avgpool 2x2 (+res) ----------------
__global__ void pool_k(const float* __restrict__ in, const float* __restrict__ res,
                       float* __restrict__ out, int total, int OH, int OW)
{
    int idx = blockIdx.x * blockDim.x + threadIdx.x;
    if (idx >= total) return;
    int ow = idx % OW, t = idx / OW, oh = t % OH, bc = t / OH;
    int IW = OW * 2;
    size_t base = (((size_t)bc * (OH * 2)) + oh * 2) * IW + ow * 2;
    float v = 0.25f * (in[base] + in[base + 1] + in[base + IW] + in[base + IW + 1]);
    if (res) v += res[idx];
    out[idx] = v;
}

// ---------------- VQ support ----------------
__global__ void xnorm_k(const float* __restrict__ h, int lhw, int N) {
    int n = blockIdx.x * blockDim.x + threadIdx.x;
    if (n >= N) return;
    int b = n >> lhw, hw = n & ((1 << lhw) - 1);
    const float* p = h + (((size_t)b * 256) << lhw) + hw;
    const size_t st = (size_t)1 << lhw;
    float s = 0.f;
#pragma unroll 8
    for (int c = 0; c < 256; c++) { float v = p[(size_t)c * st]; s += v * v; }
    g_xnorm[n] = s;
}

__global__ void vq_finish_k(int HW, int C, int do_hist) {
    __shared__ float red[256];
    int b = blockIdx.x;
    float s = 0.f;
    for (int hw = threadIdx.x; hw < HW; hw += 256) {
        int n = b * HW + hw;
        float2 c0 = g_cand[(size_t)n * 16];
        float bv = c0.x; int bi = __float_as_int(c0.y);
#pragma unroll
        for (int t = 1; t < 16; t++) {
            float2 ct = g_cand[(size_t)n * 16 + t];
            if (ct.x > bv) { bv = ct.x; bi = __float_as_int(ct.y); }
        }
        s += g_xnorm[n] - 2.f * bv;
        if (do_hist) atomicAdd(&g_hist[bi], 1);
    }
    red[threadIdx.x] = s; __syncthreads();
    for (int st = 128; st > 0; st >>= 1) {
        if (threadIdx.x < st) red[threadIdx.x] += red[threadIdx.x + st];
        __syncthreads();
    }
    if (threadIdx.x == 0) g_qloss[b] += 0.5f * red[0] / ((float)HW * (float)C);
}

__global__ void ppl_k(float* __restrict__ dout, int N) {
    __shared__ float red[256];
    float s = 0.f;
    for (int k = threadIdx.x; k < 1024; k += 256) {
        float p = (float)g_hist[k] / (float)N;
        s += p * logf(p + 1e-10f);
    }
    red[threadIdx.x] = s; __syncthreads();
    for (int st = 128; st > 0; st >>= 1) {
        if (threadIdx.x < st) red[threadIdx.x] += red[threadIdx.x + st];
        __syncthreads();
    }
    if (threadIdx.x == 0) dout[128] = expf(-red[0]);
}

// ---------------- head ----------------
__global__ void hf_k(const float* __restrict__ h) {
    int idx = blockIdx.x * blockDim.x + threadIdx.x;
    if (idx >= 64 * 256) return;
    const float* p = h + (size_t)idx * 64;
    float s = 0.f;
#pragma unroll 8
    for (int i = 0; i < 64; i++) s += fmaxf(p[i], 0.f);
    g_hf[idx] = s;
}

__global__ void final_k(const int* __restrict__ y, const float* __restrict__ lin_b,
                        float* __restrict__ dout) {
    __shared__ float red[256];
    int b = blockIdx.x, c = threadIdx.x;
    float v = g_hf[b * 256 + c];
    red[c] = v * g_swlin[c] + v * g_swemb[(size_t)y[b] * 256 + c];
    __syncthreads();
    for (int st = 128; st > 0; st >>= 1) {
        if (c < st) red[c] += red[c + st];
        __syncthreads();
    }
    if (c == 0) { dout[b] = red[0] + lin_b[0]; dout[64 + b] = g_qloss[b]; }
}

// ---------------- host ----------------
#define SYMF(x) ([]{ void* p=nullptr; cudaGetSymbolAddress(&p, x); return (float*)p; }())
#define SYMB(x) ([]{ void* p=nullptr; cudaGetSymbolAddress(&p, x); return (__nv_bfloat16*)p; }())

extern "C" void kernel_launch(void* const* d_in, const int* in_sizes, int n_in,
                              void* d_out, int out_size) {
    (void)in_sizes; (void)n_in; (void)out_size;
    const float* x      = (const float*)d_in[0];
    const int*   y      = (const int*)d_in[1];
    const float* w_raw[12] = {
        (const float*)d_in[2],  (const float*)d_in[4],  (const float*)d_in[6],
        (const float*)d_in[8],  (const float*)d_in[10], (const float*)d_in[12],
        (const float*)d_in[14], (const float*)d_in[16], (const float*)d_in[18],
        (const float*)d_in[20], (const float*)d_in[26], (const float*)d_in[28] };
    const float* b0_b1 = (const float*)d_in[3],  *b0_b2 = (const float*)d_in[5];
    const float* b0_bsc= (const float*)d_in[7],  *b1_b1 = (const float*)d_in[9];
    const float* b1_b2 = (const float*)d_in[11], *b1_bsc= (const float*)d_in[13];
    const float* b2_b1 = (const float*)d_in[15], *b2_b2 = (const float*)d_in[17];
    const float* b3_b1 = (const float*)d_in[19], *b3_b2 = (const float*)d_in[21];
    const float* cb0 = (const float*)d_in[22], *cb1 = (const float*)d_in[23];
    const float* cb2 = (const float*)d_in[24], *cb3 = (const float*)d_in[25];
    const float* lin_b = (const float*)d_in[27];
    float* dout = (float*)d_out;

    float *A = SYMF(g_A), *B = SYMF(g_B), *H0 = SYMF(g_H0), *SC = SYMF(g_SC);
    float *T8 = SYMF(g_T8), *H1 = SYMF(g_H1), *H2 = SYMF(g_H2), *H3 = SYMF(g_H3);
    float *PX = SYMF(g_PX);
    float *sw0 = SYMF(g_sw0), *sw2 = SYMF(g_sw2), *sw5 = SYMF(g_sw5);
    float *swlin = SYMF(g_swlin), *swemb = SYMF(g_swemb);
    float *en = SYMF(g_enorm4);
    __nv_bfloat16 *wbh = SYMB(g_wbh), *wbl = SYMB(g_wbl);
    __nv_bfloat16 *cbh = SYMB(g_cbh), *cbl = SYMB(g_cbl);

    const size_t WSZ = 589824u;
    SnArgs sa;
    sa.d[0]  = SnDesc{ w_raw[0],  sw0,  nullptr, nullptr, 256, 27,   1 };
    sa.d[1]  = SnDesc{ w_raw[1],  nullptr, wbh + 0*WSZ, wbl + 0*WSZ, 256, 2304, 2 };
    sa.d[2]  = SnDesc{ w_raw[2],  sw2,  nullptr, nullptr, 256, 3,    1 };
    sa.d[3]  = SnDesc{ w_raw[3],  nullptr, wbh + 1*WSZ, wbl + 1*WSZ, 256, 2304, 2 };
    sa.d[4]  = SnDesc{ w_raw[4],  nullptr, wbh + 2*WSZ, wbl + 2*WSZ, 256, 2304, 2 };
    sa.d[5]  = SnDesc{ w_raw[5],  sw5,  nullptr, nullptr, 256, 256,  1 };
    sa.d[6]  = SnDesc{ w_raw[6],  nullptr, wbh + 3*WSZ, wbl + 3*WSZ, 256, 2304, 2 };
    sa.d[7]  = SnDesc{ w_raw[7],  nullptr, wbh + 4*WSZ, wbl + 4*WSZ, 256, 2304, 2 };
    sa.d[8]  = SnDesc{ w_raw[8],  nullptr, wbh + 5*WSZ, wbl + 5*WSZ, 256, 2304, 2 };
    sa.d[9]  = SnDesc{ w_raw[9],  nullptr, wbh + 6*WSZ, wbl + 6*WSZ, 256, 2304, 2 };
    sa.d[10] = SnDesc{ w_raw[10], swlin, nullptr, nullptr, 1,   256, 0 };
    sa.d[11] = SnDesc{ w_raw[11], swemb, nullptr, nullptr, 100, 256, 0 };

    cudaFuncSetAttribute(conv_mma_k<4,32,1,64>, cudaFuncAttributeMaxDynamicSharedMemorySize, 74880);
    cudaFuncSetAttribute(conv_mma_k<8,16,1,64>, cudaFuncAttributeMaxDynamicSharedMemorySize, 72576);

    static cudaStream_t s1 = nullptr, s2 = nullptr;
    static cudaEvent_t evFork, evFin, evWall, evSC0, evH0, evSC1, evH1, evH2, evH3, evVQ;
    if (!s1) {
        cudaStreamCreateWithFlags(&s1, cudaStreamNonBlocking);
        cudaStreamCreateWithFlags(&s2, cudaStreamNonBlocking);
        cudaEventCreateWithFlags(&evFork, cudaEventDisableTiming);
        cudaEventCreateWithFlags(&evFin,  cudaEventDisableTiming);
        cudaEventCreateWithFlags(&evWall, cudaEventDisableTiming);
        cudaEventCreateWithFlags(&evSC0,  cudaEventDisableTiming);
        cudaEventCreateWithFlags(&evH0,   cudaEventDisableTiming);
        cudaEventCreateWithFlags(&evSC1,  cudaEventDisableTiming);
        cudaEventCreateWithFlags(&evH1,   cudaEventDisableTiming);
        cudaEventCreateWithFlags(&evH2,   cudaEventDisableTiming);
        cudaEventCreateWithFlags(&evH3,   cudaEventDisableTiming);
        cudaEventCreateWithFlags(&evVQ,   cudaEventDisableTiming);
    }
    cudaStream_t s0 = 0;

    // fork
    cudaEventRecord(evFork, s0);
    cudaStreamWaitEvent(s1, evFork, 0);
    cudaStreamWaitEvent(s2, evFork, 0);

    // s1: VQ prep
    init_zero_k<<<4, 256, 0, s1>>>();
    enorm_k<<<4, 256, 0, s1>>>(cb0, en + 0*1024);
    enorm_k<<<4, 256, 0, s1>>>(cb1, en + 1*1024);
    enorm_k<<<4, 256, 0, s1>>>(cb2, en + 2*1024);
    enorm_k<<<4, 256, 0, s1>>>(cb3, en + 3*1024);
    cbt_k<<<1024, 256, 0, s1>>>(cb0, cbh + 0*262144u, cbl + 0*262144u);
    cbt_k<<<1024, 256, 0, s1>>>(cb1, cbh + 1*262144u, cbl + 1*262144u);
    cbt_k<<<1024, 256, 0, s1>>>(cb2, cbh + 2*262144u, cbl + 2*262144u);
    cbt_k<<<1024, 256, 0, s1>>>(cb3, cbh + 3*262144u, cbl + 3*262144u);

    // s2: x pooling
    pool_k<<<192, 256, 0, s2>>>(x, nullptr, PX, 64*3*16*16, 16, 16);

    // s0: spectral norm (parallel); slot 0 scaled first so conv0 starts early
    sn_col_k<<<dim3(12, 8), 256, 0, s0>>>(sa);
    sn_row_k<<<dim3(12, 8), 256, 0, s0>>>(sa);
    sn_fin_k<<<1, 32, 0, s0>>>();
    cudaEventRecord(evFin, s0);
    sn_scale_k<<<dim3(1, 1), 256, 0, s0>>>(sa, 0);
    conv3x3_k<4,32,1,3><<<dim3(4, 8, 64), 256, 0, s0>>>(x, sw0, b0_b1, A, 3, 256, 32, 32, 0);

    // s2: scale remaining slots concurrently with conv0
    cudaStreamWaitEvent(s2, evFin, 0);
    sn_scale_k<<<dim3(11, 64), 256, 0, s2>>>(sa, 1);
    cudaEventRecord(evWall, s2);
    conv1x1_k<16><<<dim3(4, 128), 256, 0, s2>>>(PX, sw2, b0_bsc, SC, 3, 256, 8);
    cudaEventRecord(evSC0, s2);

    // s0: block-0 main path
    cudaStreamWaitEvent(s0, evWall, 0);
    conv_mma_k<4,32,1,64><<<dim3(4, 512), 256, 74880, s0>>>(A, wbh + 0*WSZ, wbl + 0*WSZ, b0_b2, nullptr, B, 256, 256, 32, 1);
    cudaStreamWaitEvent(s0, evSC0, 0);
    pool_k<<<16384, 256, 0, s0>>>(B, SC, H0, 64*256*16*16, 16, 16);
    cudaEventRecord(evH0, s0);

    // s1: VQ0 (HW=256)
    cudaStreamWaitEvent(s1, evH0, 0);
    xnorm_k<<<64, 256, 0, s1>>>(H0, 8, 16384);
    vq_mma_k<<<dim3(16, 128), 256, 0, s1>>>(H0, cbh + 0*262144u, cbl + 0*262144u, en + 0*1024, 256, 8);
    vq_finish_k<<<64, 256, 0, s1>>>(256, 256, 0);

    // s2: block-1 shortcut
    cudaStreamWaitEvent(s2, evH0, 0);
    pool_k<<<4096, 256, 0, s2>>>(H0, nullptr, T8, 64*256*8*8, 8, 8);
    conv1x1_k<16><<<dim3(4, 32), 256, 0, s2>>>(T8, sw5, b1_bsc, SC, 256, 256, 6);
    cudaEventRecord(evSC1, s2);

    // s0: block-1 main path
    conv_mma_k<8,16,1,64><<<dim3(4, 128), 256, 72576, s0>>>(H0, wbh + 1*WSZ, wbl + 1*WSZ, b1_b1, nullptr, A, 256, 256, 16, 1);
    conv_mma_k<8,16,1,64><<<dim3(4, 128), 256, 72576, s0>>>(A,  wbh + 2*WSZ, wbl + 2*WSZ, b1_b2, nullptr, B, 256, 256, 16, 1);
    cudaStreamWaitEvent(s0, evSC1, 0);
    pool_k<<<4096, 256, 0, s0>>>(B, SC, H1, 64*256*8*8, 8, 8);
    cudaEventRecord(evH1, s0);

    // s1: VQ1
    cudaStreamWaitEvent(s1, evH1, 0);
    xnorm_k<<<16, 256, 0, s1>>>(H1, 6, 4096);
    vq_mma_k<<<dim3(16, 32), 256, 0, s1>>>(H1, cbh + 1*262144u, cbl + 1*262144u, en + 1*1024, 256, 6);
    vq_finish_k<<<64, 256, 0, s1>>>(64, 256, 0);

    // s0: block 2 (NOC=32 -> 256 CTAs, smem < 48KB)
    conv_mma_k<8,8,2,32><<<dim3(8, 32), 256, 46848, s0>>>(H1, wbh + 3*WSZ, wbl + 3*WSZ, b2_b1, nullptr, A,  256, 256, 8, 1);
    conv_mma_k<8,8,2,32><<<dim3(8, 32), 256, 46848, s0>>>(A,  wbh + 4*WSZ, wbl + 4*WSZ, b2_b2, H1,      H2, 256, 256, 8, 1);
    cudaEventRecord(evH2, s0);

    // s1: VQ2
    cudaStreamWaitEvent(s1, evH2, 0);
    xnorm_k<<<16, 256, 0, s1>>>(H2, 6, 4096);
    vq_mma_k<<<dim3(16, 32), 256, 0, s1>>>(H2, cbh + 2*262144u, cbl + 2*262144u, en + 2*1024, 256, 6);
    vq_finish_k<<<64, 256, 0, s1>>>(64, 256, 0);

    // s0: block 3
    conv_mma_k<8,8,2,32><<<dim3(8, 32), 256, 46848, s0>>>(H2, wbh + 5*WSZ, wbl + 5*WSZ, b3_b1, nullptr, A,  256, 256, 8, 1);
    conv_mma_k<8,8,2,32><<<dim3(8, 32), 256, 46848, s0>>>(A,  wbh + 6*WSZ, wbl + 6*WSZ, b3_b2, H2,      H3, 256, 256, 8, 1);
    cudaEventRecord(evH3, s0);

    // s1: VQ3 (+hist)
    cudaStreamWaitEvent(s1, evH3, 0);
    xnorm_k<<<16, 256, 0, s1>>>(H3, 6, 4096);
    vq_mma_k<<<dim3(16, 32), 256, 0, s1>>>(H3, cbh + 3*262144u, cbl + 3*262144u, en + 3*1024, 256, 6);
    vq_finish_k<<<64, 256, 0, s1>>>(64, 256, 1);
    cudaEventRecord(evVQ, s1);

    // s0: head
    hf_k<<<64, 256, 0, s0>>>(H3);
    cudaStreamWaitEvent(s0, evVQ, 0);
    final_k<<<64, 256, 0, s0>>>(y, lin_b, dout);
    ppl_k<<<1, 256, 0, s0>>>(dout, 4096);
}